// round 17
// baseline (speedup 1.0000x reference)
#include <cuda_runtime.h>
#include <cuda_fp16.h>
#include <math.h>
#include <stdint.h>

#define BB 4
#define LL 2048
#define DD 1024
#define HH 16
#define DHH 64

typedef __half fp16;

#define LO_SCALE 1024.0f
#define LO_INV   0.0009765625f   // 1/1024

// ---------------- scratch (allocation-free device globals) ----------------
__device__ fp16 g_xh[(size_t)8192 * 1024], g_xl[(size_t)8192 * 1024];
__device__ fp16 g_wqh[(size_t)3072 * 1024], g_wql[(size_t)3072 * 1024];
__device__ fp16 g_wph[(size_t)1024 * 1024], g_wpl[(size_t)1024 * 1024];
__device__ fp16 g_qh[(size_t)64 * 2048 * 64], g_ql[(size_t)64 * 2048 * 64];
__device__ fp16 g_kh[(size_t)64 * 2048 * 64], g_kl[(size_t)64 * 2048 * 64];
__device__ fp16 g_vh[(size_t)64 * 2048 * 64], g_vl[(size_t)64 * 2048 * 64];
__device__ fp16 g_ctxh[(size_t)8192 * 1024], g_ctxl[(size_t)8192 * 1024];

// ---------------- PTX helpers ----------------
__device__ __forceinline__ uint32_t smem_u32(const void* p) {
    uint32_t a;
    asm("{ .reg .u64 t; cvta.to.shared.u64 t, %1; cvt.u32.u64 %0, t; }"
        : "=r"(a) : "l"(p));
    return a;
}
__device__ __forceinline__ void ldsm_x4(uint32_t* r, uint32_t addr) {
    asm volatile("ldmatrix.sync.aligned.m8n8.x4.shared.b16 {%0,%1,%2,%3}, [%4];"
                 : "=r"(r[0]), "=r"(r[1]), "=r"(r[2]), "=r"(r[3]) : "r"(addr));
}
__device__ __forceinline__ void ldsm_x4_t(uint32_t* r, uint32_t addr) {
    asm volatile("ldmatrix.sync.aligned.m8n8.x4.trans.shared.b16 {%0,%1,%2,%3}, [%4];"
                 : "=r"(r[0]), "=r"(r[1]), "=r"(r[2]), "=r"(r[3]) : "r"(addr));
}
// fp16 inputs, fp32 accumulate (main term)
__device__ __forceinline__ void mma_f32(float* d, const uint32_t* a,
                                        const uint32_t* b) {
    asm volatile(
        "mma.sync.aligned.m16n8k16.row.col.f32.f16.f16.f32 "
        "{%0,%1,%2,%3}, {%4,%5,%6,%7}, {%8,%9}, {%0,%1,%2,%3};"
        : "+f"(d[0]), "+f"(d[1]), "+f"(d[2]), "+f"(d[3])
        : "r"(a[0]), "r"(a[1]), "r"(a[2]), "r"(a[3]), "r"(b[0]), "r"(b[1]));
}
// fp16 inputs, fp16 accumulate (correction terms; d = 2 regs of half2)
__device__ __forceinline__ void mma_f16(uint32_t* d, const uint32_t* a,
                                        const uint32_t* b) {
    asm volatile(
        "mma.sync.aligned.m16n8k16.row.col.f16.f16.f16.f16 "
        "{%0,%1}, {%2,%3,%4,%5}, {%6,%7}, {%0,%1};"
        : "+r"(d[0]), "+r"(d[1])
        : "r"(a[0]), "r"(a[1]), "r"(a[2]), "r"(a[3]), "r"(b[0]), "r"(b[1]));
}
#define CP_ASYNC16(dst, src) \
    asm volatile("cp.async.cg.shared.global [%0], [%1], 16;" \
                 :: "r"(dst), "l"(src) : "memory")
#define CP_COMMIT() asm volatile("cp.async.commit_group;" ::: "memory")
#define CP_WAIT0()  asm volatile("cp.async.wait_group 0;" ::: "memory")

__device__ __forceinline__ uint32_t pack_h2(fp16 a, fp16 b) {
    __half2 t = __halves2half2(a, b);
    return *(uint32_t*)&t;
}
// hi = rn(v); lo = rn((v - hi) * 1024)  [lo stored pre-scaled]
__device__ __forceinline__ void split_fp16(float v, fp16& h, fp16& l) {
    h = __float2half_rn(v);
    l = __float2half_rn((v - __half2float(h)) * LO_SCALE);
}
__device__ __forceinline__ void corr_add2(float* d01, uint32_t packed) {
    __half2 t = *(__half2*)&packed;
    d01[0] += LO_INV * __low2float(t);
    d01[1] += LO_INV * __high2float(t);
}

// ---------------------------------------------------------------------------
// conv_split: fp32 -> fp16 (hi, lo*1024), elementwise
// ---------------------------------------------------------------------------
__global__ void conv_split(const float* __restrict__ src, fp16* __restrict__ h,
                           fp16* __restrict__ l, int n4)
{
    int i = blockIdx.x * blockDim.x + threadIdx.x;
    if (i >= n4) return;
    float4 v = ((const float4*)src)[i];
    fp16 h0, l0, h1, l1, h2, l2, h3, l3;
    split_fp16(v.x, h0, l0); split_fp16(v.y, h1, l1);
    split_fp16(v.z, h2, l2); split_fp16(v.w, h3, l3);
    ((__half2*)h)[2 * i]     = __halves2half2(h0, h1);
    ((__half2*)h)[2 * i + 1] = __halves2half2(h2, h3);
    ((__half2*)l)[2 * i]     = __halves2half2(l0, l1);
    ((__half2*)l)[2 * i + 1] = __halves2half2(l2, l3);
}

// ---------------------------------------------------------------------------
// HMMA GEMM, tile 128x64x32 (R16 structure): 8 warps 4x2, warp 32x32.
// Main term (hh) in f32-accum MMA; corrections (hl, lh) in f16-accum MMA.
// mode 0: scatter fp16 hi/lo into g_q/g_k/g_v (q scaled). mode 1: fp32 -> Cp.
// ---------------------------------------------------------------------------
#define GP 40  // smem pitch in fp16 elems (80 B)

__global__ __launch_bounds__(256) void hmma_gemm(
    const fp16* __restrict__ Ah_g, const fp16* __restrict__ Al_g,
    const fp16* __restrict__ Bh_g, const fp16* __restrict__ Bl_g,
    float* __restrict__ Cp, int ldc, int mode)
{
    __shared__ fp16 Ah[128][GP], Al[128][GP], Bh[64][GP], Bl[64][GP];

    const int tid  = threadIdx.x;
    const int wid  = tid >> 5;
    const int lane = tid & 31;
    const int m0   = blockIdx.y * 128;
    const int n0   = blockIdx.x * 64;
    const int wm   = (wid >> 1) * 32;   // 4 warps in m
    const int wn   = (wid & 1) * 32;    // 2 warps in n

    const uint32_t sAh = smem_u32(Ah), sAl = smem_u32(Al);
    const uint32_t sBh = smem_u32(Bh), sBl = smem_u32(Bl);

    const int arow = tid >> 2, apart = tid & 3;

    float c[2][4][4] = {};       // main accumulators (fp32)
    uint32_t cc[2][4][2] = {};   // correction accumulators (f16x2, scaled 1024x)
    uint4 pA[2][2], pB[2];

    {
        const fp16* Asrc[2] = {Ah_g, Al_g};
        const fp16* Bsrc[2] = {Bh_g, Bl_g};
        #pragma unroll
        for (int s = 0; s < 2; s++) {
            #pragma unroll
            for (int it = 0; it < 2; it++) {
                int row = arow + it * 64;
                pA[s][it] = *(const uint4*)(Asrc[s] + (size_t)(m0 + row) * 1024 + apart * 8);
            }
            pB[s] = *(const uint4*)(Bsrc[s] + (size_t)(n0 + arow) * 1024 + apart * 8);
        }
    }

    for (int ch = 0; ch < 32; ch++) {
        #pragma unroll
        for (int it = 0; it < 2; it++) {
            int row = arow + it * 64;
            *(uint4*)(&Ah[row][apart * 8]) = pA[0][it];
            *(uint4*)(&Al[row][apart * 8]) = pA[1][it];
        }
        *(uint4*)(&Bh[arow][apart * 8]) = pB[0];
        *(uint4*)(&Bl[arow][apart * 8]) = pB[1];
        __syncthreads();

        if (ch + 1 < 32) {
            const int k0 = (ch + 1) * 32;
            const fp16* Asrc[2] = {Ah_g, Al_g};
            const fp16* Bsrc[2] = {Bh_g, Bl_g};
            #pragma unroll
            for (int s = 0; s < 2; s++) {
                #pragma unroll
                for (int it = 0; it < 2; it++) {
                    int row = arow + it * 64;
                    pA[s][it] = *(const uint4*)(Asrc[s] + (size_t)(m0 + row) * 1024
                                                + k0 + apart * 8);
                }
                pB[s] = *(const uint4*)(Bsrc[s] + (size_t)(n0 + arow) * 1024
                                        + k0 + apart * 8);
            }
        }

        #pragma unroll
        for (int ks = 0; ks < 2; ks++) {
            const uint32_t kc = (uint32_t)(ks * 32 + (lane >> 4) * 16);
            uint32_t ah[2][4], al[2][4];
            #pragma unroll
            for (int mt = 0; mt < 2; mt++) {
                uint32_t off = (uint32_t)(wm + mt * 16 + (lane & 15)) * (GP * 2) + kc;
                ldsm_x4(ah[mt], sAh + off);
                ldsm_x4(al[mt], sAl + off);
            }
            uint32_t bh[4][2], bl[4][2];
            #pragma unroll
            for (int half = 0; half < 2; half++) {
                uint32_t r4h[4], r4l[4];
                uint32_t off = (uint32_t)(wn + half * 16 + (lane & 15)) * (GP * 2) + kc;
                ldsm_x4(r4h, sBh + off);
                ldsm_x4(r4l, sBl + off);
                bh[half * 2 + 0][0] = r4h[0]; bh[half * 2 + 0][1] = r4h[2];
                bh[half * 2 + 1][0] = r4h[1]; bh[half * 2 + 1][1] = r4h[3];
                bl[half * 2 + 0][0] = r4l[0]; bl[half * 2 + 0][1] = r4l[2];
                bl[half * 2 + 1][0] = r4l[1]; bl[half * 2 + 1][1] = r4l[3];
            }
            // PASS 1: main hh -> fp32 accum
            #pragma unroll
            for (int mt = 0; mt < 2; mt++)
                #pragma unroll
                for (int nt = 0; nt < 4; nt++)
                    mma_f32(c[mt][nt], ah[mt], bh[nt]);
            // PASS 2: hl corrections -> f16 accum
            #pragma unroll
            for (int mt = 0; mt < 2; mt++)
                #pragma unroll
                for (int nt = 0; nt < 4; nt++)
                    mma_f16(cc[mt][nt], ah[mt], bl[nt]);
            // PASS 3: lh corrections -> f16 accum
            #pragma unroll
            for (int mt = 0; mt < 2; mt++)
                #pragma unroll
                for (int nt = 0; nt < 4; nt++)
                    mma_f16(cc[mt][nt], al[mt], bh[nt]);
        }
        __syncthreads();
    }

    // fold corrections into fp32
    #pragma unroll
    for (int mt = 0; mt < 2; mt++)
        #pragma unroll
        for (int nt = 0; nt < 4; nt++) {
            corr_add2(&c[mt][nt][0], cc[mt][nt][0]);
            corr_add2(&c[mt][nt][2], cc[mt][nt][1]);
        }

    const int erow = lane >> 2;
    const int ecol = (lane & 3) * 2;

    if (mode == 1) {
        #pragma unroll
        for (int mt = 0; mt < 2; mt++)
            #pragma unroll
            for (int nt = 0; nt < 4; nt++) {
                int row = m0 + wm + mt * 16 + erow;
                int col = n0 + wn + nt * 8 + ecol;
                *(float2*)&Cp[(size_t)row * ldc + col] =
                    make_float2(c[mt][nt][0], c[mt][nt][1]);
                *(float2*)&Cp[(size_t)(row + 8) * ldc + col] =
                    make_float2(c[mt][nt][2], c[mt][nt][3]);
            }
    } else {
        const int which = n0 >> 10;
        fp16* dsth = (which == 0) ? g_qh : (which == 1) ? g_kh : g_vh;
        fp16* dstl = (which == 0) ? g_ql : (which == 1) ? g_kl : g_vl;
        const float sc = (which == 0) ? 0.125f : 1.0f;
        #pragma unroll
        for (int mt = 0; mt < 2; mt++)
            #pragma unroll
            for (int nt = 0; nt < 4; nt++) {
                int col = (n0 & 1023) + wn + nt * 8 + ecol;
                int h = col >> 6, dh = col & 63;
                #pragma unroll
                for (int rr = 0; rr < 2; rr++) {
                    int row = m0 + wm + mt * 16 + erow + rr * 8;
                    int b = row >> 11, l = row & 2047;
                    size_t base = ((size_t)((b << 4) + h) * 2048 + l) * 64 + dh;
                    float v0 = c[mt][nt][rr * 2 + 0] * sc;
                    float v1 = c[mt][nt][rr * 2 + 1] * sc;
                    fp16 h0, l0, h1, l1;
                    split_fp16(v0, h0, l0);
                    split_fp16(v1, h1, l1);
                    *(__half2*)(dsth + base) = __halves2half2(h0, h1);
                    *(__half2*)(dstl + base) = __halves2half2(l0, l1);
                }
            }
    }
}

// ---------------------------------------------------------------------------
// Flash attention. Main terms f32-accum; corrections f16-accum, folded
// per k-block (S before softmax; O after PV).
// ---------------------------------------------------------------------------
#define FP 72
#define FQ (128 * FP * 2)
#define FMAT (64 * FP * 2)
#define FSTAGE (4 * FMAT)
#define FLASH_SMEM (2 * FQ + 2 * FSTAGE)

__global__ __launch_bounds__(256) void flash_hmma()
{
    extern __shared__ char smem[];
    const uint32_t sb = smem_u32(smem);
    const uint32_t sQh = sb, sQl = sb + FQ;
    const uint32_t sKV = sb + 2 * FQ;

    const int tid  = threadIdx.x;
    const int wid  = tid >> 5;
    const int lane = tid & 31;
    const int bh   = blockIdx.y;
    const int q0   = blockIdx.x * 128;
    const int b    = bh >> 4;
    const int h    = bh & 15;

    const fp16* kvg[4] = {g_kh + (size_t)bh * 2048 * 64, g_kl + (size_t)bh * 2048 * 64,
                          g_vh + (size_t)bh * 2048 * 64, g_vl + (size_t)bh * 2048 * 64};

    {
        const fp16* qh_g = g_qh + (size_t)bh * 2048 * 64;
        const fp16* ql_g = g_ql + (size_t)bh * 2048 * 64;
        #pragma unroll
        for (int it = 0; it < 4; it++) {
            int i = tid + it * 256;
            int r = i >> 3, part = i & 7;
            uint4 v = *(const uint4*)(qh_g + (size_t)(q0 + r) * 64 + part * 8);
            *(uint4*)(smem + r * (FP * 2) + part * 16) = v;
            uint4 w = *(const uint4*)(ql_g + (size_t)(q0 + r) * 64 + part * 8);
            *(uint4*)(smem + FQ + r * (FP * 2) + part * 16) = w;
        }
    }

    #pragma unroll
    for (int it = 0; it < 8; it++) {
        int i = tid + it * 256;
        int mat = i >> 9, r = (i >> 3) & 63, part = i & 7;
        const fp16* src = kvg[mat] + (size_t)r * 64 + part * 8;
        uint32_t dst = sKV + mat * FMAT + r * (FP * 2) + part * 16;
        CP_ASYNC16(dst, src);
    }
    CP_COMMIT();
    __syncthreads();

    uint32_t qh[4][4], ql[4][4];
    #pragma unroll
    for (int ks = 0; ks < 4; ks++) {
        uint32_t off = (uint32_t)(wid * 16 + (lane & 15)) * (FP * 2)
                     + ks * 32 + (lane >> 4) * 16;
        ldsm_x4(qh[ks], sQh + off);
        ldsm_x4(ql[ks], sQl + off);
    }

    float o[8][4] = {};
    float mrow[2] = {-1e30f, -1e30f};
    float lrow[2] = {0.f, 0.f};

    for (int kb = 0; kb < 32; kb++) {
        CP_WAIT0();
        __syncthreads();

        if (kb + 1 < 32) {
            const uint32_t stg = sKV + ((kb + 1) & 1) * FSTAGE;
            const int krow0 = (kb + 1) * 64;
            #pragma unroll
            for (int it = 0; it < 8; it++) {
                int i = tid + it * 256;
                int mat = i >> 9, r = (i >> 3) & 63, part = i & 7;
                const fp16* src = kvg[mat] + (size_t)(krow0 + r) * 64 + part * 8;
                uint32_t dst = stg + mat * FMAT + r * (FP * 2) + part * 16;
                CP_ASYNC16(dst, src);
            }
            CP_COMMIT();
        }

        const uint32_t stg = sKV + (kb & 1) * FSTAGE;
        const uint32_t sKh = stg, sKl = stg + FMAT;
        const uint32_t sVh = stg + 2 * FMAT, sVl = stg + 3 * FMAT;

        // ---- S = Q K^T : main f32, corrections f16 ----
        float s[8][4] = {};
        uint32_t scorr[8][2] = {};
        #pragma unroll
        for (int ks = 0; ks < 4; ks++) {
            const uint32_t kc = (uint32_t)(ks * 32 + (lane >> 4) * 16);
            #pragma unroll
            for (int p = 0; p < 4; p++) {
                uint32_t kh4[4], kl4[4];
                uint32_t off = (uint32_t)(p * 16 + (lane & 15)) * (FP * 2) + kc;
                ldsm_x4(kh4, sKh + off);
                ldsm_x4(kl4, sKl + off);
                uint32_t b0h[2] = {kh4[0], kh4[2]}, b1h[2] = {kh4[1], kh4[3]};
                uint32_t b0l[2] = {kl4[0], kl4[2]}, b1l[2] = {kl4[1], kl4[3]};
                mma_f32(s[2 * p],     qh[ks], b0h);
                mma_f32(s[2 * p + 1], qh[ks], b1h);
                mma_f16(scorr[2 * p],     qh[ks], b0l);
                mma_f16(scorr[2 * p + 1], qh[ks], b1l);
                mma_f16(scorr[2 * p],     ql[ks], b0h);
                mma_f16(scorr[2 * p + 1], ql[ks], b1h);
            }
        }
        // fold S corrections
        #pragma unroll
        for (int nt = 0; nt < 8; nt++) {
            corr_add2(&s[nt][0], scorr[nt][0]);
            corr_add2(&s[nt][2], scorr[nt][1]);
        }

        // ---- online softmax ----
        #pragma unroll
        for (int rh = 0; rh < 2; rh++) {
            float mx = -1e30f;
            #pragma unroll
            for (int nt = 0; nt < 8; nt++)
                mx = fmaxf(mx, fmaxf(s[nt][2 * rh], s[nt][2 * rh + 1]));
            mx = fmaxf(mx, __shfl_xor_sync(0xffffffffu, mx, 1));
            mx = fmaxf(mx, __shfl_xor_sync(0xffffffffu, mx, 2));
            float mnew = fmaxf(mrow[rh], mx);
            float corr = __expf(mrow[rh] - mnew);
            mrow[rh] = mnew;
            float rs = 0.f;
            #pragma unroll
            for (int nt = 0; nt < 8; nt++) {
                float p0 = __expf(s[nt][2 * rh] - mnew);
                float p1 = __expf(s[nt][2 * rh + 1] - mnew);
                s[nt][2 * rh] = p0;
                s[nt][2 * rh + 1] = p1;
                rs += p0 + p1;
            }
            rs += __shfl_xor_sync(0xffffffffu, rs, 1);
            rs += __shfl_xor_sync(0xffffffffu, rs, 2);
            lrow[rh] = lrow[rh] * corr + rs;
            #pragma unroll
            for (int nt = 0; nt < 8; nt++) {
                o[nt][2 * rh]     *= corr;
                o[nt][2 * rh + 1] *= corr;
            }
        }

        // ---- P -> fp16 hi/lo fragments (lo scaled 1024x) ----
        uint32_t ph[4][4], pl[4][4];
        #pragma unroll
        for (int ks = 0; ks < 4; ks++) {
            #pragma unroll
            for (int half = 0; half < 2; half++) {
                const float* sv = s[2 * ks + half];
                #pragma unroll
                for (int rr = 0; rr < 2; rr++) {
                    float v0 = sv[2 * rr], v1 = sv[2 * rr + 1];
                    fp16 h0, l0, h1, l1;
                    split_fp16(v0, h0, l0);
                    split_fp16(v1, h1, l1);
                    ph[ks][half * 2 + rr] = pack_h2(h0, h1);
                    pl[ks][half * 2 + rr] = pack_h2(l0, l1);
                }
            }
        }

        // ---- O += P V : main f32, corrections f16 (folded per block) ----
        uint32_t ocorr[8][2] = {};
        #pragma unroll
        for (int ks = 0; ks < 4; ks++) {
            #pragma unroll
            for (int p = 0; p < 4; p++) {
                uint32_t vh4[4], vl4[4];
                uint32_t off = (uint32_t)(ks * 16 + (lane & 15)) * (FP * 2)
                             + p * 32 + (lane >> 4) * 16;
                ldsm_x4_t(vh4, sVh + off);
                ldsm_x4_t(vl4, sVl + off);
                uint32_t b0h[2] = {vh4[0], vh4[1]}, b1h[2] = {vh4[2], vh4[3]};
                uint32_t b0l[2] = {vl4[0], vl4[1]}, b1l[2] = {vl4[2], vl4[3]};
                mma_f32(o[2 * p],     ph[ks], b0h);
                mma_f32(o[2 * p + 1], ph[ks], b1h);
                mma_f16(ocorr[2 * p],     ph[ks], b0l);
                mma_f16(ocorr[2 * p + 1], ph[ks], b1l);
                mma_f16(ocorr[2 * p],     pl[ks], b0h);
                mma_f16(ocorr[2 * p + 1], pl[ks], b1h);
            }
        }
        #pragma unroll
        for (int nt = 0; nt < 8; nt++) {
            corr_add2(&o[nt][0], ocorr[nt][0]);
            corr_add2(&o[nt][2], ocorr[nt][1]);
        }
    }

    const int erow = lane >> 2;
    const int ecol = (lane & 3) * 2;
    #pragma unroll
    for (int rh = 0; rh < 2; rh++) {
        float inv = 1.f / lrow[rh];
        int row = q0 + wid * 16 + erow + rh * 8;
        size_t rbase = (size_t)(b * 2048 + row) * 1024 + h * 64;
        #pragma unroll
        for (int nt = 0; nt < 8; nt++) {
            float v0 = o[nt][2 * rh] * inv;
            float v1 = o[nt][2 * rh + 1] * inv;
            fp16 h0, l0, h1, l1;
            split_fp16(v0, h0, l0);
            split_fp16(v1, h1, l1);
            size_t idx = rbase + nt * 8 + ecol;
            *(__half2*)(g_ctxh + idx) = __halves2half2(h0, h1);
            *(__half2*)(g_ctxl + idx) = __halves2half2(l0, l1);
        }
    }
}

// ---------------------------------------------------------------------------
extern "C" void kernel_launch(void* const* d_in, const int* in_sizes, int n_in,
                              void* d_out, int out_size)
{
    const float* x      = (const float*)d_in[0];
    const float* w_qkv  = (const float*)d_in[1];
    const float* w_proj = (const float*)d_in[2];
    float* out          = (float*)d_out;

    fp16 *xh, *xl, *wqh, *wql, *wph, *wpl, *ctxh, *ctxl;
    cudaGetSymbolAddress((void**)&xh, g_xh);
    cudaGetSymbolAddress((void**)&xl, g_xl);
    cudaGetSymbolAddress((void**)&wqh, g_wqh);
    cudaGetSymbolAddress((void**)&wql, g_wql);
    cudaGetSymbolAddress((void**)&wph, g_wph);
    cudaGetSymbolAddress((void**)&wpl, g_wpl);
    cudaGetSymbolAddress((void**)&ctxh, g_ctxh);
    cudaGetSymbolAddress((void**)&ctxl, g_ctxl);

    conv_split<<<(8192 * 1024 / 4 + 255) / 256, 256>>>(x, xh, xl, 8192 * 1024 / 4);
    conv_split<<<(3072 * 1024 / 4 + 255) / 256, 256>>>(w_qkv, wqh, wql, 3072 * 1024 / 4);
    conv_split<<<(1024 * 1024 / 4 + 255) / 256, 256>>>(w_proj, wph, wpl, 1024 * 1024 / 4);

    cudaFuncSetAttribute(flash_hmma,
                         cudaFuncAttributeMaxDynamicSharedMemorySize, FLASH_SMEM);

    // QKV: M=8192, N=3072 -> grid (48, 64)
    hmma_gemm<<<dim3(48, 64), 256>>>(xh, xl, wqh, wql, nullptr, 0, 0);

    // flash: 16 q-tiles x 64 (b,h)
    flash_hmma<<<dim3(16, 64), 256, FLASH_SMEM>>>();

    // proj: M=8192, N=1024 -> grid (16, 64)
    hmma_gemm<<<dim3(16, 64), 256>>>(ctxh, ctxl, wph, wpl, out, 1024, 1);
}